// round 1
// baseline (speedup 1.0000x reference)
#include <cuda_runtime.h>

#define NN 100000
#define EE 1600000
#define DH 64
#define NB_SCAN 98   // ceil(NN/1024)

// ---------------- scratch (device globals; no allocation allowed) ------------
__device__ float g_bufA[NN * DH];
__device__ float g_bufB[NN * DH];
__device__ float g_dinv[NN];
__device__ int   g_deg[NN];
__device__ int   g_off[NN + 1];
__device__ int   g_cur[NN];
__device__ int2  g_epack[EE];     // (src, coef-bits) sorted by dst bucket
__device__ int   g_bsum[128];
__device__ int   g_boff[128];

// ---------------- graph preprocessing ---------------------------------------
__global__ void k_zero_deg() {
    int i = blockIdx.x * blockDim.x + threadIdx.x;
    if (i < NN) g_deg[i] = 0;
}

__global__ void k_count(const int* __restrict__ ei) {
    int e = blockIdx.x * blockDim.x + threadIdx.x;
    if (e < EE) atomicAdd(&g_deg[ei[EE + e]], 1);
}

__global__ void k_dinv() {
    int i = blockIdx.x * blockDim.x + threadIdx.x;
    if (i < NN) g_dinv[i] = rsqrtf((float)g_deg[i] + 1.0f);
}

// scan stage 1: per-1024-chunk sums
__global__ void k_s1() {
    int base = blockIdx.x * 1024 + threadIdx.x * 4;
    int s = 0;
#pragma unroll
    for (int j = 0; j < 4; j++) {
        int i = base + j;
        if (i < NN) s += g_deg[i];
    }
    // warp reduce
#pragma unroll
    for (int off = 16; off > 0; off >>= 1)
        s += __shfl_down_sync(0xFFFFFFFFu, s, off);
    __shared__ int ws[8];
    int wid = threadIdx.x >> 5, lane = threadIdx.x & 31;
    if (lane == 0) ws[wid] = s;
    __syncthreads();
    if (threadIdx.x == 0) {
        int t = 0;
#pragma unroll
        for (int w = 0; w < 8; w++) t += ws[w];
        g_bsum[blockIdx.x] = t;
    }
}

// scan stage 2: exclusive scan of chunk sums (1 block of 128)
__global__ void k_s2() {
    __shared__ int sh[128];
    int tid = threadIdx.x;
    int v = (tid < NB_SCAN) ? g_bsum[tid] : 0;
    sh[tid] = v;
    __syncthreads();
    for (int off = 1; off < 128; off <<= 1) {
        int t = (tid >= off) ? sh[tid - off] : 0;
        __syncthreads();
        sh[tid] += t;
        __syncthreads();
    }
    if (tid < NB_SCAN) g_boff[tid] = sh[tid] - v;
    if (tid == 0) g_off[NN] = EE;
}

// scan stage 3: full exclusive scan within each chunk + chunk offset
__global__ void k_s3() {
    int tid = threadIdx.x;
    int lane = tid & 31, wid = tid >> 5;
    int base = blockIdx.x * 1024 + tid * 4;
    int v[4];
    int s = 0;
#pragma unroll
    for (int j = 0; j < 4; j++) {
        int i = base + j;
        v[j] = (i < NN) ? g_deg[i] : 0;
        s += v[j];
    }
    int incl = s;
#pragma unroll
    for (int off = 1; off < 32; off <<= 1) {
        int t = __shfl_up_sync(0xFFFFFFFFu, incl, off);
        if (lane >= off) incl += t;
    }
    __shared__ int wsum[8], woff[8];
    if (lane == 31) wsum[wid] = incl;
    __syncthreads();
    if (tid == 0) {
        int run = 0;
#pragma unroll
        for (int w = 0; w < 8; w++) { woff[w] = run; run += wsum[w]; }
    }
    __syncthreads();
    int excl = g_boff[blockIdx.x] + woff[wid] + incl - s;
#pragma unroll
    for (int j = 0; j < 4; j++) {
        int i = base + j;
        if (i < NN) { g_off[i] = excl; g_cur[i] = excl; }
        excl += v[j];
    }
}

__global__ void k_fill(const int* __restrict__ ei) {
    int e = blockIdx.x * blockDim.x + threadIdx.x;
    if (e >= EE) return;
    int s = ei[e];
    int d = ei[EE + e];
    int p = atomicAdd(&g_cur[d], 1);
    float c = g_dinv[s] * g_dinv[d];
    g_epack[p] = make_int2(s, __float_as_int(c));
}

// ---------------- aggregation: warp per node ---------------------------------
__global__ void k_agg(const float* __restrict__ h, float* __restrict__ out,
                      const float* __restrict__ bias) {
    int w = (blockIdx.x * blockDim.x + threadIdx.x) >> 5;
    int lane = threadIdx.x & 31;
    if (w >= NN) return;
    int e = g_off[w];
    int end = g_off[w + 1];
    float a0 = 0.f, a1 = 0.f;
    for (; e < end; e++) {
        int2 p = g_epack[e];
        float c = __int_as_float(p.y);
        const float* hr = h + (size_t)p.x * DH;
        a0 = fmaf(hr[lane], c, a0);
        a1 = fmaf(hr[lane + 32], c, a1);
    }
    float dn = g_dinv[w];
    float d2 = dn * dn;
    const float* hs = h + (size_t)w * DH;
    a0 = fmaf(hs[lane], d2, a0) + bias[lane];
    a1 = fmaf(hs[lane + 32], d2, a1) + bias[lane + 32];
    out[(size_t)w * DH + lane]      = fmaxf(a0, 0.f);
    out[(size_t)w * DH + lane + 32] = fmaxf(a1, 0.f);
}

// ---------------- GEMM 64x64 (tile 64 rows) ----------------------------------
template <bool BIAS, bool RELU>
__global__ void k_gemm64(const float* __restrict__ X, const float* __restrict__ W,
                         const float* __restrict__ b, float* __restrict__ Y) {
    __shared__ float xs[64 * 64];
    __shared__ float wsm[64 * 64];
    __shared__ float bs[64];
    int tid = threadIdx.x;
    int rowBlock = blockIdx.x * 64;

    const float4* W4 = (const float4*)W;
    float4* ws4 = (float4*)wsm;
#pragma unroll
    for (int i = tid; i < 1024; i += 256) ws4[i] = W4[i];

    float4* xs4 = (float4*)xs;
    const float4* X4 = (const float4*)X;
#pragma unroll
    for (int i = tid; i < 1024; i += 256) {
        int r = i >> 4;
        int gr = rowBlock + r;
        xs4[i] = (gr < NN) ? X4[(size_t)gr * 16 + (i & 15)]
                           : make_float4(0.f, 0.f, 0.f, 0.f);
    }
    if (BIAS && tid < 64) bs[tid] = b[tid];
    __syncthreads();

    int cg = tid & 15;          // float4 column group (cols cg*4..cg*4+3)
    int r0 = (tid >> 4) * 4;    // 4 rows per thread
    float4 a0 = make_float4(0.f, 0.f, 0.f, 0.f), a1 = a0, a2 = a0, a3 = a0;

#pragma unroll
    for (int k = 0; k < 64; k++) {
        float4 w = ws4[k * 16 + cg];
        float x0 = xs[(r0 + 0) * 64 + k];
        float x1 = xs[(r0 + 1) * 64 + k];
        float x2 = xs[(r0 + 2) * 64 + k];
        float x3 = xs[(r0 + 3) * 64 + k];
        a0.x = fmaf(x0, w.x, a0.x); a0.y = fmaf(x0, w.y, a0.y);
        a0.z = fmaf(x0, w.z, a0.z); a0.w = fmaf(x0, w.w, a0.w);
        a1.x = fmaf(x1, w.x, a1.x); a1.y = fmaf(x1, w.y, a1.y);
        a1.z = fmaf(x1, w.z, a1.z); a1.w = fmaf(x1, w.w, a1.w);
        a2.x = fmaf(x2, w.x, a2.x); a2.y = fmaf(x2, w.y, a2.y);
        a2.z = fmaf(x2, w.z, a2.z); a2.w = fmaf(x2, w.w, a2.w);
        a3.x = fmaf(x3, w.x, a3.x); a3.y = fmaf(x3, w.y, a3.y);
        a3.z = fmaf(x3, w.z, a3.z); a3.w = fmaf(x3, w.w, a3.w);
    }

    float4 acc[4] = {a0, a1, a2, a3};
    float4* Y4 = (float4*)Y;
#pragma unroll
    for (int i = 0; i < 4; i++) {
        int gr = rowBlock + r0 + i;
        if (gr < NN) {
            float4 v = acc[i];
            if (BIAS) {
                v.x += bs[cg * 4 + 0]; v.y += bs[cg * 4 + 1];
                v.z += bs[cg * 4 + 2]; v.w += bs[cg * 4 + 3];
            }
            if (RELU) {
                v.x = fmaxf(v.x, 0.f); v.y = fmaxf(v.y, 0.f);
                v.z = fmaxf(v.z, 0.f); v.w = fmaxf(v.w, 0.f);
            }
            Y4[(size_t)gr * 16 + cg] = v;
        }
    }
}

// ---------------- GEMM 64x16 (final layer, bias, no relu) --------------------
__global__ void k_gemm16(const float* __restrict__ X, const float* __restrict__ W,
                         const float* __restrict__ b, float* __restrict__ Y) {
    __shared__ float xs[64 * 64];
    __shared__ float wsm[64 * 16];
    __shared__ float bs[16];
    int tid = threadIdx.x;
    int rowBlock = blockIdx.x * 64;

    float4* ws4 = (float4*)wsm;
    const float4* W4 = (const float4*)W;
    if (tid < 256) ws4[tid] = W4[tid];

    float4* xs4 = (float4*)xs;
    const float4* X4 = (const float4*)X;
#pragma unroll
    for (int i = tid; i < 1024; i += 256) {
        int r = i >> 4;
        int gr = rowBlock + r;
        xs4[i] = (gr < NN) ? X4[(size_t)gr * 16 + (i & 15)]
                           : make_float4(0.f, 0.f, 0.f, 0.f);
    }
    if (tid < 16) bs[tid] = b[tid];
    __syncthreads();

    int row = tid >> 2;   // 64 rows
    int cg = tid & 3;     // 4 float4 col groups = 16 cols
    float4 acc = make_float4(0.f, 0.f, 0.f, 0.f);
#pragma unroll
    for (int k = 0; k < 64; k++) {
        float4 w = ws4[k * 4 + cg];
        float x = xs[row * 64 + k];
        acc.x = fmaf(x, w.x, acc.x);
        acc.y = fmaf(x, w.y, acc.y);
        acc.z = fmaf(x, w.z, acc.z);
        acc.w = fmaf(x, w.w, acc.w);
    }
    int gr = rowBlock + row;
    if (gr < NN) {
        acc.x += bs[cg * 4 + 0]; acc.y += bs[cg * 4 + 1];
        acc.z += bs[cg * 4 + 2]; acc.w += bs[cg * 4 + 3];
        ((float4*)Y)[(size_t)gr * 4 + cg] = acc;
    }
}

// ---------------- launch ------------------------------------------------------
extern "C" void kernel_launch(void* const* d_in, const int* in_sizes, int n_in,
                              void* d_out, int out_size) {
    const float* x   = (const float*)d_in[0];
    const int*   ei  = (const int*)d_in[1];
    const float* W1  = (const float*)d_in[2];
    const float* b1  = (const float*)d_in[3];
    const float* W2  = (const float*)d_in[4];
    const float* b2  = (const float*)d_in[5];
    const float* W3  = (const float*)d_in[6];
    const float* b3  = (const float*)d_in[7];
    const float* Wf1 = (const float*)d_in[8];
    const float* bf1 = (const float*)d_in[9];
    const float* Wf2 = (const float*)d_in[10];
    const float* bf2 = (const float*)d_in[11];
    float* out = (float*)d_out;

    void *pA_, *pB_;
    cudaGetSymbolAddress(&pA_, g_bufA);
    cudaGetSymbolAddress(&pB_, g_bufB);
    float* A = (float*)pA_;
    float* B = (float*)pB_;

    int nblkN = (NN + 255) / 256;
    int nblkE = (EE + 255) / 256;
    int nblkG = (NN + 63) / 64;
    int nblkAgg = (NN * 32 + 255) / 256;

    // graph preprocessing (structure shared by all 3 conv layers)
    k_zero_deg<<<nblkN, 256>>>();
    k_count<<<nblkE, 256>>>(ei);
    k_dinv<<<nblkN, 256>>>();
    k_s1<<<NB_SCAN, 256>>>();
    k_s2<<<1, 128>>>();
    k_s3<<<NB_SCAN, 256>>>();
    k_fill<<<nblkE, 256>>>(ei);

    // layer 1
    k_gemm64<false, false><<<nblkG, 256>>>(x, W1, nullptr, A);
    k_agg<<<nblkAgg, 256>>>(A, B, b1);
    // layer 2
    k_gemm64<false, false><<<nblkG, 256>>>(B, W2, nullptr, A);
    k_agg<<<nblkAgg, 256>>>(A, B, b2);
    // layer 3
    k_gemm64<false, false><<<nblkG, 256>>>(B, W3, nullptr, A);
    k_agg<<<nblkAgg, 256>>>(A, B, b3);
    // ffn
    k_gemm64<true, true><<<nblkG, 256>>>(B, Wf1, bf1, A);
    k_gemm16<<<nblkG, 256>>>(A, Wf2, bf2, out);
}

// round 4
// speedup vs baseline: 1.0015x; 1.0015x over previous
#include <cuda_runtime.h>
#include <cuda_fp16.h>

#define NN 100000
#define EE 1600000
#define DH 64
#define NB_SCAN 98   // ceil(NN/1024)

// ---------------- scratch (device globals; no allocation allowed) ------------
__device__ __half g_h[NN * DH];      // fp16 feature rows for aggregation
__device__ float  g_bufA[NN * DH];
__device__ float  g_bufB[NN * DH];
__device__ float  g_dinv[NN];
__device__ int    g_deg[NN];
__device__ int    g_off[NN + 1];
__device__ int    g_cur[NN];
__device__ int2   g_epack[EE];       // (src, coef-bits) sorted by dst bucket
__device__ int    g_bsum[128];
__device__ int    g_boff[128];

// ---------------- graph preprocessing ---------------------------------------
__global__ void k_zero_deg() {
    int i = blockIdx.x * blockDim.x + threadIdx.x;
    if (i < NN) g_deg[i] = 0;
}

__global__ void k_count(const int* __restrict__ ei) {
    int e = blockIdx.x * blockDim.x + threadIdx.x;
    if (e < EE) atomicAdd(&g_deg[ei[EE + e]], 1);
}

// scan stage 1: per-1024-chunk sums
__global__ void k_s1() {
    int base = blockIdx.x * 1024 + threadIdx.x * 4;
    int s = 0;
#pragma unroll
    for (int j = 0; j < 4; j++) {
        int i = base + j;
        if (i < NN) s += g_deg[i];
    }
#pragma unroll
    for (int off = 16; off > 0; off >>= 1)
        s += __shfl_down_sync(0xFFFFFFFFu, s, off);
    __shared__ int ws[8];
    int wid = threadIdx.x >> 5, lane = threadIdx.x & 31;
    if (lane == 0) ws[wid] = s;
    __syncthreads();
    if (threadIdx.x == 0) {
        int t = 0;
#pragma unroll
        for (int w = 0; w < 8; w++) t += ws[w];
        g_bsum[blockIdx.x] = t;
    }
}

// scan stage 2: exclusive scan of chunk sums (1 block of 128)
__global__ void k_s2() {
    __shared__ int sh[128];
    int tid = threadIdx.x;
    int v = (tid < NB_SCAN) ? g_bsum[tid] : 0;
    sh[tid] = v;
    __syncthreads();
    for (int off = 1; off < 128; off <<= 1) {
        int t = (tid >= off) ? sh[tid - off] : 0;
        __syncthreads();
        sh[tid] += t;
        __syncthreads();
    }
    if (tid < NB_SCAN) g_boff[tid] = sh[tid] - v;
    if (tid == 0) g_off[NN] = EE;
}

// scan stage 3: exclusive scan within chunk + chunk offset; also dinv
__global__ void k_s3() {
    int tid = threadIdx.x;
    int lane = tid & 31, wid = tid >> 5;
    int base = blockIdx.x * 1024 + tid * 4;
    int v[4];
    int s = 0;
#pragma unroll
    for (int j = 0; j < 4; j++) {
        int i = base + j;
        v[j] = (i < NN) ? g_deg[i] : 0;
        s += v[j];
    }
    int incl = s;
#pragma unroll
    for (int off = 1; off < 32; off <<= 1) {
        int t = __shfl_up_sync(0xFFFFFFFFu, incl, off);
        if (lane >= off) incl += t;
    }
    __shared__ int wsum[8], woff[8];
    if (lane == 31) wsum[wid] = incl;
    __syncthreads();
    if (tid == 0) {
        int run = 0;
#pragma unroll
        for (int w = 0; w < 8; w++) { woff[w] = run; run += wsum[w]; }
    }
    __syncthreads();
    int excl = g_boff[blockIdx.x] + woff[wid] + incl - s;
#pragma unroll
    for (int j = 0; j < 4; j++) {
        int i = base + j;
        if (i < NN) {
            g_off[i] = excl;
            g_cur[i] = excl;
            g_dinv[i] = rsqrtf((float)v[j] + 1.0f);
        }
        excl += v[j];
    }
}

__global__ void k_fill(const int* __restrict__ ei) {
    int e = blockIdx.x * blockDim.x + threadIdx.x;
    if (e >= EE) return;
    int s = ei[e];
    int d = ei[EE + e];
    int p = atomicAdd(&g_cur[d], 1);
    float c = g_dinv[s] * g_dinv[d];
    g_epack[p] = make_int2(s, __float_as_int(c));
}

// ---------------- aggregation: warp per node, fp16 rows, unroll 4 ------------
__global__ void k_agg(const __half2* __restrict__ h, float* __restrict__ out,
                      const float* __restrict__ bias) {
    int w = (blockIdx.x * blockDim.x + threadIdx.x) >> 5;
    int lane = threadIdx.x & 31;
    if (w >= NN) return;
    int e = g_off[w];
    int end = g_off[w + 1];
    float a0 = 0.f, a1 = 0.f;

    for (; e + 4 <= end; e += 4) {
        int2 p0 = g_epack[e + 0];
        int2 p1 = g_epack[e + 1];
        int2 p2 = g_epack[e + 2];
        int2 p3 = g_epack[e + 3];
        __half2 r0 = h[p0.x * 32 + lane];
        __half2 r1 = h[p1.x * 32 + lane];
        __half2 r2 = h[p2.x * 32 + lane];
        __half2 r3 = h[p3.x * 32 + lane];
        float2 f0 = __half22float2(r0);
        float2 f1 = __half22float2(r1);
        float2 f2 = __half22float2(r2);
        float2 f3 = __half22float2(r3);
        float c0 = __int_as_float(p0.y);
        float c1 = __int_as_float(p1.y);
        float c2 = __int_as_float(p2.y);
        float c3 = __int_as_float(p3.y);
        a0 = fmaf(f0.x, c0, a0); a1 = fmaf(f0.y, c0, a1);
        a0 = fmaf(f1.x, c1, a0); a1 = fmaf(f1.y, c1, a1);
        a0 = fmaf(f2.x, c2, a0); a1 = fmaf(f2.y, c2, a1);
        a0 = fmaf(f3.x, c3, a0); a1 = fmaf(f3.y, c3, a1);
    }
    for (; e < end; e++) {
        int2 p = g_epack[e];
        float c = __int_as_float(p.y);
        float2 f = __half22float2(h[p.x * 32 + lane]);
        a0 = fmaf(f.x, c, a0);
        a1 = fmaf(f.y, c, a1);
    }

    float dn = g_dinv[w];
    float d2 = dn * dn;
    float2 fs = __half22float2(h[w * 32 + lane]);
    a0 = fmaf(fs.x, d2, a0) + bias[2 * lane + 0];
    a1 = fmaf(fs.y, d2, a1) + bias[2 * lane + 1];
    float2 o;
    o.x = fmaxf(a0, 0.f);
    o.y = fmaxf(a1, 0.f);
    ((float2*)out)[(size_t)w * 32 + lane] = o;
}

// ---------------- GEMM 64x64 -------------------------------------------------
// OUT_HALF: write fp16 rows (no bias/relu — applied in agg).
// else: fp32 with optional bias+relu (FFN layer).
template <bool OUT_HALF, bool BIAS, bool RELU>
__global__ void k_gemm64(const float* __restrict__ X, const float* __restrict__ W,
                         const float* __restrict__ b, void* __restrict__ Yv) {
    __shared__ float xs[64 * 64];
    __shared__ float wsm[64 * 64];
    __shared__ float bs[64];
    int tid = threadIdx.x;
    int rowBlock = blockIdx.x * 64;

    const float4* W4 = (const float4*)W;
    float4* ws4 = (float4*)wsm;
#pragma unroll
    for (int i = tid; i < 1024; i += 256) ws4[i] = W4[i];

    float4* xs4 = (float4*)xs;
    const float4* X4 = (const float4*)X;
#pragma unroll
    for (int i = tid; i < 1024; i += 256) {
        int r = i >> 4;
        int gr = rowBlock + r;
        xs4[i] = (gr < NN) ? X4[(size_t)gr * 16 + (i & 15)]
                           : make_float4(0.f, 0.f, 0.f, 0.f);
    }
    if (BIAS && tid < 64) bs[tid] = b[tid];
    __syncthreads();

    int cg = tid & 15;          // float4 column group (cols cg*4..cg*4+3)
    int r0 = (tid >> 4) * 4;    // 4 rows per thread
    float4 a0 = make_float4(0.f, 0.f, 0.f, 0.f), a1 = a0, a2 = a0, a3 = a0;

#pragma unroll
    for (int k = 0; k < 64; k++) {
        float4 w = ws4[k * 16 + cg];
        float x0 = xs[(r0 + 0) * 64 + k];
        float x1 = xs[(r0 + 1) * 64 + k];
        float x2 = xs[(r0 + 2) * 64 + k];
        float x3 = xs[(r0 + 3) * 64 + k];
        a0.x = fmaf(x0, w.x, a0.x); a0.y = fmaf(x0, w.y, a0.y);
        a0.z = fmaf(x0, w.z, a0.z); a0.w = fmaf(x0, w.w, a0.w);
        a1.x = fmaf(x1, w.x, a1.x); a1.y = fmaf(x1, w.y, a1.y);
        a1.z = fmaf(x1, w.z, a1.z); a1.w = fmaf(x1, w.w, a1.w);
        a2.x = fmaf(x2, w.x, a2.x); a2.y = fmaf(x2, w.y, a2.y);
        a2.z = fmaf(x2, w.z, a2.z); a2.w = fmaf(x2, w.w, a2.w);
        a3.x = fmaf(x3, w.x, a3.x); a3.y = fmaf(x3, w.y, a3.y);
        a3.z = fmaf(x3, w.z, a3.z); a3.w = fmaf(x3, w.w, a3.w);
    }

    float4 acc[4] = {a0, a1, a2, a3};
#pragma unroll
    for (int i = 0; i < 4; i++) {
        int gr = rowBlock + r0 + i;
        if (gr < NN) {
            float4 v = acc[i];
            if (OUT_HALF) {
                __half2 h0 = __floats2half2_rn(v.x, v.y);
                __half2 h1 = __floats2half2_rn(v.z, v.w);
                uint2 u;
                u.x = *(unsigned int*)&h0;
                u.y = *(unsigned int*)&h1;
                ((uint2*)((__half*)Yv + (size_t)gr * 64))[cg] = u;
            } else {
                if (BIAS) {
                    v.x += bs[cg * 4 + 0]; v.y += bs[cg * 4 + 1];
                    v.z += bs[cg * 4 + 2]; v.w += bs[cg * 4 + 3];
                }
                if (RELU) {
                    v.x = fmaxf(v.x, 0.f); v.y = fmaxf(v.y, 0.f);
                    v.z = fmaxf(v.z, 0.f); v.w = fmaxf(v.w, 0.f);
                }
                ((float4*)Yv)[(size_t)gr * 16 + cg] = v;
            }
        }
    }
}

// ---------------- GEMM 64x16 (final layer, bias, no relu) --------------------
__global__ void k_gemm16(const float* __restrict__ X, const float* __restrict__ W,
                         const float* __restrict__ b, float* __restrict__ Y) {
    __shared__ float xs[64 * 64];
    __shared__ float wsm[64 * 16];
    __shared__ float bs[16];
    int tid = threadIdx.x;
    int rowBlock = blockIdx.x * 64;

    float4* ws4 = (float4*)wsm;
    const float4* W4 = (const float4*)W;
    if (tid < 256) ws4[tid] = W4[tid];

    float4* xs4 = (float4*)xs;
    const float4* X4 = (const float4*)X;
#pragma unroll
    for (int i = tid; i < 1024; i += 256) {
        int r = i >> 4;
        int gr = rowBlock + r;
        xs4[i] = (gr < NN) ? X4[(size_t)gr * 16 + (i & 15)]
                           : make_float4(0.f, 0.f, 0.f, 0.f);
    }
    if (tid < 16) bs[tid] = b[tid];
    __syncthreads();

    int row = tid >> 2;   // 64 rows
    int cg = tid & 3;     // 4 float4 col groups = 16 cols
    float4 acc = make_float4(0.f, 0.f, 0.f, 0.f);
#pragma unroll
    for (int k = 0; k < 64; k++) {
        float4 w = ws4[k * 4 + cg];
        float x = xs[row * 64 + k];
        acc.x = fmaf(x, w.x, acc.x);
        acc.y = fmaf(x, w.y, acc.y);
        acc.z = fmaf(x, w.z, acc.z);
        acc.w = fmaf(x, w.w, acc.w);
    }
    int gr = rowBlock + row;
    if (gr < NN) {
        acc.x += bs[cg * 4 + 0]; acc.y += bs[cg * 4 + 1];
        acc.z += bs[cg * 4 + 2]; acc.w += bs[cg * 4 + 3];
        ((float4*)Y)[(size_t)gr * 4 + cg] = acc;
    }
}

// ---------------- launch ------------------------------------------------------
extern "C" void kernel_launch(void* const* d_in, const int* in_sizes, int n_in,
                              void* d_out, int out_size) {
    const float* x   = (const float*)d_in[0];
    const int*   ei  = (const int*)d_in[1];
    const float* W1  = (const float*)d_in[2];
    const float* b1  = (const float*)d_in[3];
    const float* W2  = (const float*)d_in[4];
    const float* b2  = (const float*)d_in[5];
    const float* W3  = (const float*)d_in[6];
    const float* b3  = (const float*)d_in[7];
    const float* Wf1 = (const float*)d_in[8];
    const float* bf1 = (const float*)d_in[9];
    const float* Wf2 = (const float*)d_in[10];
    const float* bf2 = (const float*)d_in[11];
    float* out = (float*)d_out;

    void *pH_, *pA_, *pB_;
    cudaGetSymbolAddress(&pH_, g_h);
    cudaGetSymbolAddress(&pA_, g_bufA);
    cudaGetSymbolAddress(&pB_, g_bufB);
    __half* H = (__half*)pH_;
    float* A = (float*)pA_;
    float* B = (float*)pB_;

    int nblkN = (NN + 255) / 256;
    int nblkE = (EE + 255) / 256;
    int nblkG = (NN + 63) / 64;
    int nblkAgg = (NN * 32 + 255) / 256;

    // graph preprocessing (structure shared by all 3 conv layers)
    k_zero_deg<<<nblkN, 256>>>();
    k_count<<<nblkE, 256>>>(ei);
    k_s1<<<NB_SCAN, 256>>>();
    k_s2<<<1, 128>>>();
    k_s3<<<NB_SCAN, 256>>>();
    k_fill<<<nblkE, 256>>>(ei);

    // layer 1
    k_gemm64<true, false, false><<<nblkG, 256>>>(x, W1, nullptr, H);
    k_agg<<<nblkAgg, 256>>>((const __half2*)H, B, b1);
    // layer 2
    k_gemm64<true, false, false><<<nblkG, 256>>>(B, W2, nullptr, H);
    k_agg<<<nblkAgg, 256>>>((const __half2*)H, B, b2);
    // layer 3
    k_gemm64<true, false, false><<<nblkG, 256>>>(B, W3, nullptr, H);
    k_agg<<<nblkAgg, 256>>>((const __half2*)H, B, b3);
    // ffn
    k_gemm64<false, true, true><<<nblkG, 256>>>(B, Wf1, bf1, A);
    k_gemm16<<<nblkG, 256>>>(A, Wf2, bf2, out);
}